// round 15
// baseline (speedup 1.0000x reference)
#include <cuda_runtime.h>
#include <cuda_fp16.h>
#include <cstdint>

#define TOKENS 32768
#define HID 768
#define INTR 3072
#define NTAGS 64

// ---------------------------------------------------------------------------
// Scratch (static device memory — allocation-free per harness rules)
// ---------------------------------------------------------------------------
__device__ __align__(256) __half g_x[(size_t)TOKENS * HID];    // LN1 out (fp16)
__device__ __align__(256) __half g_h[(size_t)TOKENS * INTR];   // relu(x@W1+b1) fp16
__device__ __align__(256) __half g_ffx[(size_t)TOKENS * HID];  // ff + x (fp16)
__device__ __align__(256) __half g_w1t[(size_t)INTR * HID];    // W1^T [n][k] fp16
__device__ __align__(256) __half g_w2t[(size_t)HID * INTR];    // W2^T [n][k] fp16
__device__ __align__(256) float  g_tmp[NTAGS * HID];           // tag_emb@Wv+bv
__device__ __align__(256) float  g_ptag[NTAGS * HID];          // per-tag vector

// ---------------------------------------------------------------------------
// Helpers
// ---------------------------------------------------------------------------
__device__ __forceinline__ void cp_async16(uint32_t saddr, const void* gaddr) {
    asm volatile("cp.async.cg.shared.global [%0], [%1], 16;" :: "r"(saddr), "l"(gaddr));
}
__device__ __forceinline__ void cp_commit() { asm volatile("cp.async.commit_group;"); }
template<int N> __device__ __forceinline__ void cp_wait() {
    asm volatile("cp.async.wait_group %0;" :: "n"(N));
}

__device__ __forceinline__ void mma_f16(float c[4], const uint32_t a[4],
                                        uint32_t b0, uint32_t b1) {
    asm volatile(
        "mma.sync.aligned.m16n8k16.row.col.f32.f16.f16.f32 "
        "{%0,%1,%2,%3}, {%4,%5,%6,%7}, {%8,%9}, {%0,%1,%2,%3};"
        : "+f"(c[0]), "+f"(c[1]), "+f"(c[2]), "+f"(c[3])
        : "r"(a[0]), "r"(a[1]), "r"(a[2]), "r"(a[3]), "r"(b0), "r"(b1));
}

__device__ __forceinline__ void ldsm_x4(uint32_t r[4], uint32_t addr) {
    asm volatile("ldmatrix.sync.aligned.m8n8.x4.shared.b16 {%0,%1,%2,%3}, [%4];"
        : "=r"(r[0]), "=r"(r[1]), "=r"(r[2]), "=r"(r[3]) : "r"(addr));
}

// ---------------------------------------------------------------------------
// Fused prep kernel: weight transpose+round -> half [n][k], plus tag GEMV tail
// ---------------------------------------------------------------------------
template<int WHICH, int K, int N>
__global__ void __launch_bounds__(256)
prep_kernel(const float* __restrict__ W,
            const float* __restrict__ E,
            const float* __restrict__ Wt,
            const float* __restrict__ bt) {
    __shared__ float sbuf[32 * 33];
    constexpr int TB = (N / 32) * (K / 32);
    const int tid = threadIdx.x;
    const int bid = blockIdx.x;

    if (bid < TB) {
        int nb = bid % (N / 32), kb = bid / (N / 32);
        int tx = tid & 31, ty = tid >> 5;
        float (*tile)[33] = (float(*)[33])sbuf;
#pragma unroll
        for (int i = ty; i < 32; i += 8)
            tile[i][tx] = W[(long)(kb * 32 + i) * N + nb * 32 + tx];
        __syncthreads();
        __half* out = WHICH ? g_w2t : g_w1t;
#pragma unroll
        for (int i = ty; i < 32; i += 8)
            out[(long)(nb * 32 + i) * K + kb * 32 + tx] = __float2half_rn(tile[tx][i]);
    } else {
        int b2 = bid - TB;
        int t = b2 / 3, chunk = b2 - t * 3;
        int n = chunk * 256 + tid;
        const float* Es = WHICH ? g_tmp : E;
        float* O = WHICH ? g_ptag : g_tmp;
        for (int c = tid; c < HID; c += 256) sbuf[c] = Es[t * HID + c];
        __syncthreads();
        float a0 = bt[n], a1 = 0.f, a2 = 0.f, a3 = 0.f;
        for (int k = 0; k < HID; k += 8) {
            float w0 = Wt[(long)(k + 0) * HID + n];
            float w1 = Wt[(long)(k + 1) * HID + n];
            float w2 = Wt[(long)(k + 2) * HID + n];
            float w3 = Wt[(long)(k + 3) * HID + n];
            float w4 = Wt[(long)(k + 4) * HID + n];
            float w5 = Wt[(long)(k + 5) * HID + n];
            float w6 = Wt[(long)(k + 6) * HID + n];
            float w7 = Wt[(long)(k + 7) * HID + n];
            a0 = fmaf(sbuf[k + 0], w0, a0);
            a1 = fmaf(sbuf[k + 1], w1, a1);
            a2 = fmaf(sbuf[k + 2], w2, a2);
            a3 = fmaf(sbuf[k + 3], w3, a3);
            a0 = fmaf(sbuf[k + 4], w4, a0);
            a1 = fmaf(sbuf[k + 5], w5, a1);
            a2 = fmaf(sbuf[k + 6], w6, a2);
            a3 = fmaf(sbuf[k + 7], w7, a3);
        }
        O[t * HID + n] = (a0 + a1) + (a2 + a3);
    }
}

// ---------------------------------------------------------------------------
// Block reduce for (sum, sumsq) over 192 threads (6 warps)
// ---------------------------------------------------------------------------
__device__ __forceinline__ void block_reduce2_192(float& s, float& s2, float* red) {
#pragma unroll
    for (int o = 16; o > 0; o >>= 1) {
        s  += __shfl_xor_sync(0xffffffffu, s,  o);
        s2 += __shfl_xor_sync(0xffffffffu, s2, o);
    }
    int warp = threadIdx.x >> 5, lane = threadIdx.x & 31;
    if (lane == 0) { red[warp] = s; red[6 + warp] = s2; }
    __syncthreads();
    if (warp == 0) {
        float a  = (lane < 6) ? red[lane] : 0.f;
        float a2 = (lane < 6) ? red[6 + lane] : 0.f;
#pragma unroll
        for (int o = 4; o > 0; o >>= 1) {
            a  += __shfl_xor_sync(0xffffffffu, a,  o);
            a2 += __shfl_xor_sync(0xffffffffu, a2, o);
        }
        if (lane == 0) { red[12] = a; red[13] = a2; }
    }
    __syncthreads();
    s = red[12]; s2 = red[13];
}

// ---------------------------------------------------------------------------
// LN1 (vectorized): g_x = fp16_rn( LN( we + ptag[tag]*mask ) * g + b )
// ---------------------------------------------------------------------------
__global__ void __launch_bounds__(192)
ln1_kernel(const float* __restrict__ we, const int* __restrict__ tags,
           const int* __restrict__ mask,
           const float* __restrict__ g, const float* __restrict__ b) {
    __shared__ float red[14];
    long row = blockIdx.x;
    int t = threadIdx.x;
    float mk = (float)mask[row];
    float4 w4 = *(const float4*)(we + row * HID + t * 4);
    float4 p4 = *(const float4*)(g_ptag + (long)tags[row] * HID + t * 4);
    float v[4] = { w4.x + p4.x * mk, w4.y + p4.y * mk,
                   w4.z + p4.z * mk, w4.w + p4.w * mk };
    float s = (v[0] + v[1]) + (v[2] + v[3]);
    float s2 = (v[0] * v[0] + v[1] * v[1]) + (v[2] * v[2] + v[3] * v[3]);
    block_reduce2_192(s, s2, red);
    float mu = s * (1.f / 768.f);
    float var = s2 * (1.f / 768.f) - mu * mu;
    float rs = rsqrtf(var + 1e-12f);
    float4 g4 = *(const float4*)(g + t * 4);
    float4 b4 = *(const float4*)(b + t * 4);
    __half2 o0, o1;
    o0.x = __float2half_rn((v[0] - mu) * rs * g4.x + b4.x);
    o0.y = __float2half_rn((v[1] - mu) * rs * g4.y + b4.y);
    o1.x = __float2half_rn((v[2] - mu) * rs * g4.z + b4.z);
    o1.y = __float2half_rn((v[3] - mu) * rs * g4.w + b4.w);
    __half2* dst = (__half2*)(g_x + row * HID + t * 4);
    dst[0] = o0; dst[1] = o1;
}

// ---------------------------------------------------------------------------
// LN2 (vectorized): out = LN(g_ffx fp16) * g + b   (fp32 output)
// ---------------------------------------------------------------------------
__global__ void __launch_bounds__(192)
ln2_kernel(const float* __restrict__ g, const float* __restrict__ b,
           float* __restrict__ out) {
    __shared__ float red[14];
    long row = blockIdx.x;
    int t = threadIdx.x;
    const __half2* src = (const __half2*)(g_ffx + row * HID + t * 4);
    float2 a0 = __half22float2(src[0]);
    float2 a1 = __half22float2(src[1]);
    float v[4] = { a0.x, a0.y, a1.x, a1.y };
    float s = (v[0] + v[1]) + (v[2] + v[3]);
    float s2 = (v[0] * v[0] + v[1] * v[1]) + (v[2] * v[2] + v[3] * v[3]);
    block_reduce2_192(s, s2, red);
    float mu = s * (1.f / 768.f);
    float var = s2 * (1.f / 768.f) - mu * mu;
    float rs = rsqrtf(var + 1e-12f);
    float4 g4 = *(const float4*)(g + t * 4);
    float4 b4 = *(const float4*)(b + t * 4);
    float4 o;
    o.x = (v[0] - mu) * rs * g4.x + b4.x;
    o.y = (v[1] - mu) * rs * g4.y + b4.y;
    o.z = (v[2] - mu) * rs * g4.z + b4.z;
    o.w = (v[3] - mu) * rs * g4.w + b4.w;
    *(float4*)(out + row * HID + t * 4) = o;
}

// ---------------------------------------------------------------------------
// fp16 mma.sync GEMM: 128x128 CTA tile, 128 threads = 4 warps of 64x64 (2x2).
//   MODE 0: A=g_x,  Bt=g_w1t, C=g_h   (half), epi = fp16_rn(relu(acc+bias))
//   MODE 1: A=g_h,  Bt=g_w2t, C=g_ffx (half), epi = acc+bias+float(g_x)
// BK=64 halves, XOR swizzle, ldmatrix.x4, NS=3 ring, race-fixed cross-tile
// fragment prefetch (R14). NEW in R15:
//  * REVERSED row order (y -> gridDim.y-1-y): first waves read the rows the
//    producer kernel wrote LAST, which are still L2-resident (g_h = 201 MB >
//    L2, so ascending order reads the coldest rows first). Also aligns
//    reversed gemm2's last-written rows with forward ln2's first reads.
//  * Epilogue bias values hoisted (were reloaded 8x per thread).
// ---------------------------------------------------------------------------
template<int MODE, int N, int K>
__global__ void __launch_bounds__(128, 2)
hgemm_kernel(const float* __restrict__ bias) {
    constexpr int BM = 128, BK = 64;             // BK in halves; 128 B per row
    constexpr int ABYTES = BM * BK * 2;          // 16 KB
    constexpr int STG = 2 * ABYTES;              // A + B = 32 KB per stage
    constexpr int NS = 3;                        // 96 KB smem per CTA

    extern __shared__ __align__(16) char smem_raw[];

    const __half* A  = MODE ? g_h   : g_x;
    const __half* Bt = MODE ? g_w2t : g_w1t;

    const int tid = threadIdx.x;
    const int lane = tid & 31;
    const int warp = tid >> 5;                   // 0..3
    const int wr = (warp & 1) * 64;              // warp row (0/64)
    const int wc = (warp >> 1) * 64;             // warp col (0/64)
    // Reversed row order for producer->consumer L2 temporal locality.
    const long blockRow = (long)(gridDim.y - 1 - blockIdx.y) * BM;
    const int  blockCol = blockIdx.x * 128;

    float acc[4][8][4];
#pragma unroll
    for (int mi = 0; mi < 4; mi++)
#pragma unroll
        for (int ni = 0; ni < 8; ni++)
#pragma unroll
            for (int r = 0; r < 4; r++) acc[mi][ni][r] = 0.f;

    const uint32_t sbase = (uint32_t)__cvta_generic_to_shared(smem_raw);

    // ldmatrix lane mappings (validated R8..R14) — hoisted once.
    const int  rA_lane = wr + (lane & 15);
    const uint32_t eA = (uint32_t)(lane >> 4);
    const int  rB_lane = wc + ((lane & 16) >> 1) + (lane & 7);
    const uint32_t eB = (uint32_t)((lane >> 3) & 1);
    uint32_t aOff[4], aKey[4], bOff[4], bKey[4];
#pragma unroll
    for (int mi = 0; mi < 4; mi++) {
        int r = rA_lane + mi * 16;
        aOff[mi] = (uint32_t)(r * 128);
        aKey[mi] = (uint32_t)(r & 7);
    }
#pragma unroll
    for (int p = 0; p < 4; p++) {
        int r = rB_lane + p * 16;
        bOff[p] = (uint32_t)(r * 128);
        bKey[p] = (uint32_t)(r & 7);
    }

    auto load_tile = [&](int kt, int st) {
        uint32_t base = sbase + (uint32_t)st * STG;
#pragma unroll
        for (int i = 0; i < 8; i++) {            // A: 1024 chunks / 128 thr
            int idx = tid + i * 128;
            int r = idx >> 3, c = idx & 7;
            const __half* gp = A + (blockRow + r) * (long)K + kt * BK + c * 8;
            cp_async16(base + (uint32_t)(r * 128 + ((c ^ (r & 7)) << 4)), gp);
        }
#pragma unroll
        for (int i = 0; i < 8; i++) {            // B: 1024 chunks / 128 thr
            int idx = tid + i * 128;
            int r = idx >> 3, c = idx & 7;
            const __half* gp = Bt + (long)(blockCol + r) * K + kt * BK + c * 8;
            cp_async16(base + ABYTES + (uint32_t)(r * 128 + ((c ^ (r & 7)) << 4)), gp);
        }
        cp_commit();
    };

    // Fragment double-buffer (per k16 step; buf0 always holds step 0).
    uint32_t af[2][4][4], bf[2][4][4];
    auto ldfrags = [&](uint32_t sa, int s, int buf) {
        const uint32_t sb = sa + ABYTES;
        const uint32_t cA = (uint32_t)(s * 2) + eA;
        const uint32_t cB = (uint32_t)(s * 2) + eB;
#pragma unroll
        for (int mi = 0; mi < 4; mi++)
            ldsm_x4(af[buf][mi], sa + aOff[mi] + ((cA ^ aKey[mi]) << 4));
#pragma unroll
        for (int p = 0; p < 4; p++)
            ldsm_x4(bf[buf][p], sb + bOff[p] + ((cB ^ bKey[p]) << 4));
    };

    load_tile(0, 0);
    load_tile(1, 1);
    cp_wait<1>();                                // this thread's tile-0 copies done
    __syncthreads();                             // ...made CTA-visible
    ldfrags(sbase, 0, 0);                        // preload tile 0 step 0 (safe)

    const int kTiles = K / BK;                   // 12 or 48
    for (int t = 0; t < kTiles; t++) {
        // Stage (t+2)%3 == (t-1)%3: all its readers passed the previous
        // end-of-iteration barrier, so overwriting is safe.
        if (t + 2 < kTiles) load_tile(t + 2, (t + 2) % NS);
        else cp_commit();                        // keep group arithmetic exact

        const uint32_t sa = sbase + (uint32_t)(t % NS) * STG;
#pragma unroll
        for (int s = 0; s < 4; s++) {
            if (s < 3) ldfrags(sa, s + 1, (s + 1) & 1);   // next-step prefetch
            const int b = s & 1;
#pragma unroll
            for (int mi = 0; mi < 4; mi++) {
#pragma unroll
                for (int p = 0; p < 4; p++) {
                    mma_f16(acc[mi][2 * p + 0], af[b][mi], bf[b][p][0], bf[b][p][1]);
                    mma_f16(acc[mi][2 * p + 1], af[b][mi], bf[b][p][2], bf[b][p][3]);
                }
            }
        }
        // Race-fixed cross-tile prefetch: wait + BARRIER, then read.
        if (t + 1 < kTiles) {
            cp_wait<1>();                        // tile t+1: this thread done
            __syncthreads();                     // all threads done -> visible
            ldfrags(sbase + (uint32_t)((t + 1) % NS) * STG, 0, 0);
        }
    }

    // ---- Epilogue (bias hoisted: mi/ri-invariant) ----
    float bs0[8], bs1[8];
#pragma unroll
    for (int ni = 0; ni < 8; ni++) {
        int col = blockCol + wc + ni * 8 + (lane & 3) * 2;
        bs0[ni] = bias[col];
        bs1[ni] = bias[col + 1];
    }
#pragma unroll
    for (int mi = 0; mi < 4; mi++) {
#pragma unroll
        for (int ri = 0; ri < 2; ri++) {
            long row = blockRow + wr + mi * 16 + (lane >> 2) + ri * 8;
#pragma unroll
            for (int ni = 0; ni < 8; ni++) {
                int col = blockCol + wc + ni * 8 + (lane & 3) * 2;
                float v0 = acc[mi][ni][ri * 2 + 0] + bs0[ni];
                float v1 = acc[mi][ni][ri * 2 + 1] + bs1[ni];
                __half2 h2;
                if (MODE == 0) {
                    h2.x = __float2half_rn(fmaxf(v0, 0.f));
                    h2.y = __float2half_rn(fmaxf(v1, 0.f));
                    *(__half2*)(g_h + row * (long)N + col) = h2;
                } else {
                    __half2 x2 = *(const __half2*)(g_x + row * HID + col);
                    h2.x = __float2half_rn(v0 + __half2float(x2.x));
                    h2.y = __float2half_rn(v1 + __half2float(x2.y));
                    *(__half2*)(g_ffx + row * (long)N + col) = h2;
                }
            }
        }
    }
}

// ---------------------------------------------------------------------------
// Launch  (order keeps gemm1 at the ncu-captured slot #4)
// ---------------------------------------------------------------------------
extern "C" void kernel_launch(void* const* d_in, const int* in_sizes, int n_in,
                              void* d_out, int out_size) {
    const float* we      = (const float*)d_in[0];
    const int*   tags    = (const int*)d_in[1];
    const int*   mask    = (const int*)d_in[2];
    const float* tag_emb = (const float*)d_in[3];
    const float* Wv      = (const float*)d_in[4];
    const float* bv      = (const float*)d_in[5];
    const float* Wo      = (const float*)d_in[6];
    const float* bo      = (const float*)d_in[7];
    const float* ln1g    = (const float*)d_in[8];
    const float* ln1b    = (const float*)d_in[9];
    const float* W1      = (const float*)d_in[10];
    const float* b1      = (const float*)d_in[11];
    const float* W2      = (const float*)d_in[12];
    const float* b2      = (const float*)d_in[13];
    const float* ln2g    = (const float*)d_in[14];
    const float* ln2b    = (const float*)d_in[15];
    float* out = (float*)d_out;

    const int smem_bytes = 3 * 2 * 128 * 64 * 2;   // 98304 B (3 stages x 32 KB)
    cudaFuncSetAttribute(hgemm_kernel<0, INTR, HID>,
                         cudaFuncAttributeMaxDynamicSharedMemorySize, smem_bytes);
    cudaFuncSetAttribute(hgemm_kernel<1, HID, INTR>,
                         cudaFuncAttributeMaxDynamicSharedMemorySize, smem_bytes);

    prep_kernel<0, HID, INTR><<<2304 + 192, 256>>>(W1, tag_emb, Wv, bv);
    prep_kernel<1, INTR, HID><<<2304 + 192, 256>>>(W2, nullptr, Wo, bo);

    ln1_kernel<<<TOKENS, 192>>>(we, tags, mask, ln1g, ln1b);

    hgemm_kernel<0, INTR, HID>
        <<<dim3(INTR / 128, TOKENS / 128), 128, smem_bytes>>>(b1);

    hgemm_kernel<1, HID, INTR>
        <<<dim3(HID / 128, TOKENS / 128), 128, smem_bytes>>>(b2);

    ln2_kernel<<<TOKENS, 192>>>(ln2g, ln2b, out);
}

// round 16
// speedup vs baseline: 1.0084x; 1.0084x over previous
#include <cuda_runtime.h>
#include <cuda_fp16.h>
#include <cstdint>

#define TOKENS 32768
#define HID 768
#define INTR 3072
#define NTAGS 64

// ---------------------------------------------------------------------------
// Scratch (static device memory — allocation-free per harness rules)
// ---------------------------------------------------------------------------
__device__ __align__(256) __half g_x[(size_t)TOKENS * HID];    // LN1 out (fp16)
__device__ __align__(256) __half g_h[(size_t)TOKENS * INTR];   // relu(x@W1+b1) fp16
__device__ __align__(256) __half g_ffx[(size_t)TOKENS * HID];  // ff + x (fp16)
__device__ __align__(256) __half g_w1t[(size_t)INTR * HID];    // W1^T [n][k] fp16
__device__ __align__(256) __half g_w2t[(size_t)HID * INTR];    // W2^T [n][k] fp16
__device__ __align__(256) float  g_tmp[NTAGS * HID];           // tag_emb@Wv+bv
__device__ __align__(256) float  g_ptag[NTAGS * HID];          // per-tag vector

// ---------------------------------------------------------------------------
// Helpers
// ---------------------------------------------------------------------------
__device__ __forceinline__ void cp_async16(uint32_t saddr, const void* gaddr) {
    asm volatile("cp.async.cg.shared.global [%0], [%1], 16;" :: "r"(saddr), "l"(gaddr));
}
__device__ __forceinline__ void cp_commit() { asm volatile("cp.async.commit_group;"); }
template<int N> __device__ __forceinline__ void cp_wait() {
    asm volatile("cp.async.wait_group %0;" :: "n"(N));
}

__device__ __forceinline__ void mma_f16(float c[4], const uint32_t a[4],
                                        uint32_t b0, uint32_t b1) {
    asm volatile(
        "mma.sync.aligned.m16n8k16.row.col.f32.f16.f16.f32 "
        "{%0,%1,%2,%3}, {%4,%5,%6,%7}, {%8,%9}, {%0,%1,%2,%3};"
        : "+f"(c[0]), "+f"(c[1]), "+f"(c[2]), "+f"(c[3])
        : "r"(a[0]), "r"(a[1]), "r"(a[2]), "r"(a[3]), "r"(b0), "r"(b1));
}

__device__ __forceinline__ void ldsm_x4(uint32_t r[4], uint32_t addr) {
    asm volatile("ldmatrix.sync.aligned.m8n8.x4.shared.b16 {%0,%1,%2,%3}, [%4];"
        : "=r"(r[0]), "=r"(r[1]), "=r"(r[2]), "=r"(r[3]) : "r"(addr));
}

// ---------------------------------------------------------------------------
// Fused prep kernel: weight transpose+round -> half [n][k], plus tag GEMV tail
// ---------------------------------------------------------------------------
template<int WHICH, int K, int N>
__global__ void __launch_bounds__(256)
prep_kernel(const float* __restrict__ W,
            const float* __restrict__ E,
            const float* __restrict__ Wt,
            const float* __restrict__ bt) {
    __shared__ float sbuf[32 * 33];
    constexpr int TB = (N / 32) * (K / 32);
    const int tid = threadIdx.x;
    const int bid = blockIdx.x;

    if (bid < TB) {
        int nb = bid % (N / 32), kb = bid / (N / 32);
        int tx = tid & 31, ty = tid >> 5;
        float (*tile)[33] = (float(*)[33])sbuf;
#pragma unroll
        for (int i = ty; i < 32; i += 8)
            tile[i][tx] = W[(long)(kb * 32 + i) * N + nb * 32 + tx];
        __syncthreads();
        __half* out = WHICH ? g_w2t : g_w1t;
#pragma unroll
        for (int i = ty; i < 32; i += 8)
            out[(long)(nb * 32 + i) * K + kb * 32 + tx] = __float2half_rn(tile[tx][i]);
    } else {
        int b2 = bid - TB;
        int t = b2 / 3, chunk = b2 - t * 3;
        int n = chunk * 256 + tid;
        const float* Es = WHICH ? g_tmp : E;
        float* O = WHICH ? g_ptag : g_tmp;
        for (int c = tid; c < HID; c += 256) sbuf[c] = Es[t * HID + c];
        __syncthreads();
        float a0 = bt[n], a1 = 0.f, a2 = 0.f, a3 = 0.f;
        for (int k = 0; k < HID; k += 8) {
            float w0 = Wt[(long)(k + 0) * HID + n];
            float w1 = Wt[(long)(k + 1) * HID + n];
            float w2 = Wt[(long)(k + 2) * HID + n];
            float w3 = Wt[(long)(k + 3) * HID + n];
            float w4 = Wt[(long)(k + 4) * HID + n];
            float w5 = Wt[(long)(k + 5) * HID + n];
            float w6 = Wt[(long)(k + 6) * HID + n];
            float w7 = Wt[(long)(k + 7) * HID + n];
            a0 = fmaf(sbuf[k + 0], w0, a0);
            a1 = fmaf(sbuf[k + 1], w1, a1);
            a2 = fmaf(sbuf[k + 2], w2, a2);
            a3 = fmaf(sbuf[k + 3], w3, a3);
            a0 = fmaf(sbuf[k + 4], w4, a0);
            a1 = fmaf(sbuf[k + 5], w5, a1);
            a2 = fmaf(sbuf[k + 6], w6, a2);
            a3 = fmaf(sbuf[k + 7], w7, a3);
        }
        O[t * HID + n] = (a0 + a1) + (a2 + a3);
    }
}

// ---------------------------------------------------------------------------
// Block reduce for (sum, sumsq) over 192 threads (6 warps)
// ---------------------------------------------------------------------------
__device__ __forceinline__ void block_reduce2_192(float& s, float& s2, float* red) {
#pragma unroll
    for (int o = 16; o > 0; o >>= 1) {
        s  += __shfl_xor_sync(0xffffffffu, s,  o);
        s2 += __shfl_xor_sync(0xffffffffu, s2, o);
    }
    int warp = threadIdx.x >> 5, lane = threadIdx.x & 31;
    if (lane == 0) { red[warp] = s; red[6 + warp] = s2; }
    __syncthreads();
    if (warp == 0) {
        float a  = (lane < 6) ? red[lane] : 0.f;
        float a2 = (lane < 6) ? red[6 + lane] : 0.f;
#pragma unroll
        for (int o = 4; o > 0; o >>= 1) {
            a  += __shfl_xor_sync(0xffffffffu, a,  o);
            a2 += __shfl_xor_sync(0xffffffffu, a2, o);
        }
        if (lane == 0) { red[12] = a; red[13] = a2; }
    }
    __syncthreads();
    s = red[12]; s2 = red[13];
}

// ---------------------------------------------------------------------------
// LN1 (vectorized): g_x = fp16_rn( LN( we + ptag[tag]*mask ) * g + b )
// ---------------------------------------------------------------------------
__global__ void __launch_bounds__(192)
ln1_kernel(const float* __restrict__ we, const int* __restrict__ tags,
           const int* __restrict__ mask,
           const float* __restrict__ g, const float* __restrict__ b) {
    __shared__ float red[14];
    long row = blockIdx.x;
    int t = threadIdx.x;
    float mk = (float)mask[row];
    float4 w4 = *(const float4*)(we + row * HID + t * 4);
    float4 p4 = *(const float4*)(g_ptag + (long)tags[row] * HID + t * 4);
    float v[4] = { w4.x + p4.x * mk, w4.y + p4.y * mk,
                   w4.z + p4.z * mk, w4.w + p4.w * mk };
    float s = (v[0] + v[1]) + (v[2] + v[3]);
    float s2 = (v[0] * v[0] + v[1] * v[1]) + (v[2] * v[2] + v[3] * v[3]);
    block_reduce2_192(s, s2, red);
    float mu = s * (1.f / 768.f);
    float var = s2 * (1.f / 768.f) - mu * mu;
    float rs = rsqrtf(var + 1e-12f);
    float4 g4 = *(const float4*)(g + t * 4);
    float4 b4 = *(const float4*)(b + t * 4);
    __half2 o0, o1;
    o0.x = __float2half_rn((v[0] - mu) * rs * g4.x + b4.x);
    o0.y = __float2half_rn((v[1] - mu) * rs * g4.y + b4.y);
    o1.x = __float2half_rn((v[2] - mu) * rs * g4.z + b4.z);
    o1.y = __float2half_rn((v[3] - mu) * rs * g4.w + b4.w);
    __half2* dst = (__half2*)(g_x + row * HID + t * 4);
    dst[0] = o0; dst[1] = o1;
}

// ---------------------------------------------------------------------------
// LN2 (vectorized): out = LN(g_ffx fp16) * g + b   (fp32 output)
// ---------------------------------------------------------------------------
__global__ void __launch_bounds__(192)
ln2_kernel(const float* __restrict__ g, const float* __restrict__ b,
           float* __restrict__ out) {
    __shared__ float red[14];
    long row = blockIdx.x;
    int t = threadIdx.x;
    const __half2* src = (const __half2*)(g_ffx + row * HID + t * 4);
    float2 a0 = __half22float2(src[0]);
    float2 a1 = __half22float2(src[1]);
    float v[4] = { a0.x, a0.y, a1.x, a1.y };
    float s = (v[0] + v[1]) + (v[2] + v[3]);
    float s2 = (v[0] * v[0] + v[1] * v[1]) + (v[2] * v[2] + v[3] * v[3]);
    block_reduce2_192(s, s2, red);
    float mu = s * (1.f / 768.f);
    float var = s2 * (1.f / 768.f) - mu * mu;
    float rs = rsqrtf(var + 1e-12f);
    float4 g4 = *(const float4*)(g + t * 4);
    float4 b4 = *(const float4*)(b + t * 4);
    float4 o;
    o.x = (v[0] - mu) * rs * g4.x + b4.x;
    o.y = (v[1] - mu) * rs * g4.y + b4.y;
    o.z = (v[2] - mu) * rs * g4.z + b4.z;
    o.w = (v[3] - mu) * rs * g4.w + b4.w;
    *(float4*)(out + row * HID + t * 4) = o;
}

// ---------------------------------------------------------------------------
// fp16 mma.sync GEMM: 128xBN CTA tile, 128 threads = 4 warps of 64x(BN/2).
//   MODE 0: A=g_x,  Bt=g_w1t, C=g_h   (half), epi = fp16_rn(relu(acc+bias))
//   MODE 1: A=g_h,  Bt=g_w2t, C=g_ffx (half), epi = acc+bias+float(g_x)
// BK=64 halves, XOR swizzle, ldmatrix.x4, NS=3 ring, race-fixed cross-tile
// fragment prefetch (R14 schedule, forward row order — R15 reversal reverted).
// BN is a template param: gemm1 uses 128 (grid 6144 = 20.8 waves, loss ~1%);
// gemm2 uses 96 (grid 2048 = 6.92 waves vs 5.19 at BN=128 -> wave-
// quantization loss 13% -> 1%).
// ---------------------------------------------------------------------------
template<int MODE, int BN, int N, int K>
__global__ void __launch_bounds__(128, 2)
hgemm_kernel(const float* __restrict__ bias) {
    constexpr int BM = 128, BK = 64;             // BK in halves; 128 B per row
    constexpr int ABYTES = BM * BK * 2;          // 16 KB
    constexpr int BBYTES = BN * BK * 2;          // 16 or 12 KB
    constexpr int STG = ABYTES + BBYTES;         // per-stage bytes
    constexpr int NS = 3;
    constexpr int NP = BN / 32;                  // B ldsm groups (4 or 3)
    constexpr int NI = BN / 16;                  // acc col blocks (8 or 6)
    constexpr int BCH = BN * 8 / 128;            // B chunks per thread (8 or 6)

    extern __shared__ __align__(16) char smem_raw[];

    const __half* A  = MODE ? g_h   : g_x;
    const __half* Bt = MODE ? g_w2t : g_w1t;

    const int tid = threadIdx.x;
    const int lane = tid & 31;
    const int warp = tid >> 5;                   // 0..3
    const int wr = (warp & 1) * 64;              // warp row (0/64)
    const int wc = (warp >> 1) * (BN / 2);       // warp col (0 / BN/2)
    const long blockRow = (long)blockIdx.y * BM;
    const int  blockCol = blockIdx.x * BN;

    float acc[4][NI][4];
#pragma unroll
    for (int mi = 0; mi < 4; mi++)
#pragma unroll
        for (int ni = 0; ni < NI; ni++)
#pragma unroll
            for (int r = 0; r < 4; r++) acc[mi][ni][r] = 0.f;

    const uint32_t sbase = (uint32_t)__cvta_generic_to_shared(smem_raw);

    // ldmatrix lane mappings (validated R8..R14) — hoisted once.
    const int  rA_lane = wr + (lane & 15);
    const uint32_t eA = (uint32_t)(lane >> 4);
    const int  rB_lane = wc + ((lane & 16) >> 1) + (lane & 7);
    const uint32_t eB = (uint32_t)((lane >> 3) & 1);
    uint32_t aOff[4], aKey[4], bOff[NP], bKey[NP];
#pragma unroll
    for (int mi = 0; mi < 4; mi++) {
        int r = rA_lane + mi * 16;
        aOff[mi] = (uint32_t)(r * 128);
        aKey[mi] = (uint32_t)(r & 7);
    }
#pragma unroll
    for (int p = 0; p < NP; p++) {
        int r = rB_lane + p * 16;
        bOff[p] = (uint32_t)(r * 128);
        bKey[p] = (uint32_t)(r & 7);
    }

    auto load_tile = [&](int kt, int st) {
        uint32_t base = sbase + (uint32_t)st * STG;
#pragma unroll
        for (int i = 0; i < 8; i++) {            // A: 1024 chunks / 128 thr
            int idx = tid + i * 128;
            int r = idx >> 3, c = idx & 7;
            const __half* gp = A + (blockRow + r) * (long)K + kt * BK + c * 8;
            cp_async16(base + (uint32_t)(r * 128 + ((c ^ (r & 7)) << 4)), gp);
        }
#pragma unroll
        for (int i = 0; i < BCH; i++) {          // B: BN*8 chunks / 128 thr
            int idx = tid + i * 128;
            int r = idx >> 3, c = idx & 7;
            const __half* gp = Bt + (long)(blockCol + r) * K + kt * BK + c * 8;
            cp_async16(base + ABYTES + (uint32_t)(r * 128 + ((c ^ (r & 7)) << 4)), gp);
        }
        cp_commit();
    };

    // Fragment double-buffer (per k16 step; buf0 always holds step 0).
    uint32_t af[2][4][4], bf[2][NP][4];
    auto ldfrags = [&](uint32_t sa, int s, int buf) {
        const uint32_t sb = sa + ABYTES;
        const uint32_t cA = (uint32_t)(s * 2) + eA;
        const uint32_t cB = (uint32_t)(s * 2) + eB;
#pragma unroll
        for (int mi = 0; mi < 4; mi++)
            ldsm_x4(af[buf][mi], sa + aOff[mi] + ((cA ^ aKey[mi]) << 4));
#pragma unroll
        for (int p = 0; p < NP; p++)
            ldsm_x4(bf[buf][p], sb + bOff[p] + ((cB ^ bKey[p]) << 4));
    };

    load_tile(0, 0);
    load_tile(1, 1);
    cp_wait<1>();                                // this thread's tile-0 copies done
    __syncthreads();                             // ...made CTA-visible
    ldfrags(sbase, 0, 0);                        // preload tile 0 step 0 (safe)

    const int kTiles = K / BK;                   // 12 or 48
    for (int t = 0; t < kTiles; t++) {
        // Stage (t+2)%3 == (t-1)%3: all its readers passed the previous
        // end-of-iteration barrier, so overwriting is safe.
        if (t + 2 < kTiles) load_tile(t + 2, (t + 2) % NS);
        else cp_commit();                        // keep group arithmetic exact

        const uint32_t sa = sbase + (uint32_t)(t % NS) * STG;
#pragma unroll
        for (int s = 0; s < 4; s++) {
            if (s < 3) ldfrags(sa, s + 1, (s + 1) & 1);   // next-step prefetch
            const int b = s & 1;
#pragma unroll
            for (int mi = 0; mi < 4; mi++) {
#pragma unroll
                for (int p = 0; p < NP; p++) {
                    mma_f16(acc[mi][2 * p + 0], af[b][mi], bf[b][p][0], bf[b][p][1]);
                    mma_f16(acc[mi][2 * p + 1], af[b][mi], bf[b][p][2], bf[b][p][3]);
                }
            }
        }
        // Race-fixed cross-tile prefetch: wait + BARRIER, then read.
        if (t + 1 < kTiles) {
            cp_wait<1>();                        // tile t+1: this thread done
            __syncthreads();                     // all threads done -> visible
            ldfrags(sbase + (uint32_t)((t + 1) % NS) * STG, 0, 0);
        }
    }

    // ---- Epilogue (bias hoisted: mi/ri-invariant) ----
    float bs0[NI], bs1[NI];
#pragma unroll
    for (int ni = 0; ni < NI; ni++) {
        int col = blockCol + wc + ni * 8 + (lane & 3) * 2;
        bs0[ni] = bias[col];
        bs1[ni] = bias[col + 1];
    }
#pragma unroll
    for (int mi = 0; mi < 4; mi++) {
#pragma unroll
        for (int ri = 0; ri < 2; ri++) {
            long row = blockRow + wr + mi * 16 + (lane >> 2) + ri * 8;
#pragma unroll
            for (int ni = 0; ni < NI; ni++) {
                int col = blockCol + wc + ni * 8 + (lane & 3) * 2;
                float v0 = acc[mi][ni][ri * 2 + 0] + bs0[ni];
                float v1 = acc[mi][ni][ri * 2 + 1] + bs1[ni];
                __half2 h2;
                if (MODE == 0) {
                    h2.x = __float2half_rn(fmaxf(v0, 0.f));
                    h2.y = __float2half_rn(fmaxf(v1, 0.f));
                    *(__half2*)(g_h + row * (long)N + col) = h2;
                } else {
                    __half2 x2 = *(const __half2*)(g_x + row * HID + col);
                    h2.x = __float2half_rn(v0 + __half2float(x2.x));
                    h2.y = __float2half_rn(v1 + __half2float(x2.y));
                    *(__half2*)(g_ffx + row * (long)N + col) = h2;
                }
            }
        }
    }
}

// ---------------------------------------------------------------------------
// Launch  (order keeps gemm1 at the ncu-captured slot #4)
// ---------------------------------------------------------------------------
extern "C" void kernel_launch(void* const* d_in, const int* in_sizes, int n_in,
                              void* d_out, int out_size) {
    const float* we      = (const float*)d_in[0];
    const int*   tags    = (const int*)d_in[1];
    const int*   mask    = (const int*)d_in[2];
    const float* tag_emb = (const float*)d_in[3];
    const float* Wv      = (const float*)d_in[4];
    const float* bv      = (const float*)d_in[5];
    const float* Wo      = (const float*)d_in[6];
    const float* bo      = (const float*)d_in[7];
    const float* ln1g    = (const float*)d_in[8];
    const float* ln1b    = (const float*)d_in[9];
    const float* W1      = (const float*)d_in[10];
    const float* b1      = (const float*)d_in[11];
    const float* W2      = (const float*)d_in[12];
    const float* b2      = (const float*)d_in[13];
    const float* ln2g    = (const float*)d_in[14];
    const float* ln2b    = (const float*)d_in[15];
    float* out = (float*)d_out;

    const int smem1 = 3 * (128 * 64 * 2 + 128 * 64 * 2);   // 98304 B (BN=128)
    const int smem2 = 3 * (128 * 64 * 2 + 96 * 64 * 2);    // 86016 B (BN=96)
    cudaFuncSetAttribute(hgemm_kernel<0, 128, INTR, HID>,
                         cudaFuncAttributeMaxDynamicSharedMemorySize, smem1);
    cudaFuncSetAttribute(hgemm_kernel<1, 96, HID, INTR>,
                         cudaFuncAttributeMaxDynamicSharedMemorySize, smem2);

    prep_kernel<0, HID, INTR><<<2304 + 192, 256>>>(W1, tag_emb, Wv, bv);
    prep_kernel<1, INTR, HID><<<2304 + 192, 256>>>(W2, nullptr, Wo, bo);

    ln1_kernel<<<TOKENS, 192>>>(we, tags, mask, ln1g, ln1b);

    // GEMM1: [32768,768]@[768,3072], BN=128 (20.8 waves, ~1% tail loss)
    hgemm_kernel<0, 128, INTR, HID>
        <<<dim3(INTR / 128, TOKENS / 128), 128, smem1>>>(b1);

    // GEMM2: [32768,3072]@[3072,768], BN=96 (6.92 waves vs 5.19@BN=128)
    hgemm_kernel<1, 96, HID, INTR>
        <<<dim3(HID / 96, TOKENS / 128), 128, smem2>>>(b2);

    ln2_kernel<<<TOKENS, 192>>>(ln2g, ln2b, out);
}